// round 1
// baseline (speedup 1.0000x reference)
#include <cuda_runtime.h>

// Problem shape (fixed by the dataset): B=16, T=8192, N=32, depth=31.
constexpr int N_STACK = 32;
constexpr int DEPTH   = 31;

__device__ __forceinline__ float clip_log(float l) {
    // tanh(l/10)*10 computed as 10*(e^{2x}-1)/(e^{2x}+1), x = l/10.
    // |l| <= ~30 everywhere it is called -> e^{2x} <= ~e^6, no overflow.
    float t = __expf(l * 0.2f);
    return 10.0f * __fdividef(t - 1.0f, t + 1.0f);
}

// add_log_space(sx,lx,sy,ly) exactly mirroring the reference branch structure,
// computed branchlessly (all paths evaluated, predicated selects).
__device__ __forceinline__ void add_log(float sx, float lx, float sy, float ly,
                                        float& so, float& lo) {
    bool zx = (sx == 0.0f);
    bool zy = (sy == 0.0f);

    // same-sign branch: sign(sx), clip(logaddexp(lx,ly))
    float mx = fmaxf(lx, ly);
    float mn = fminf(lx, ly);
    float l_same = clip_log(mx + __logf(1.0f + __expf(mn - mx)));
    float s_same = (sx > 0.0f) ? 1.0f : ((sx < 0.0f) ? -1.0f : 0.0f);

    // opposite-sign branch: big + log1p(-exp(clip(small-big, -10, -0.001)))
    bool  bx    = (lx >= ly);
    float big   = bx ? lx : ly;
    float small = bx ? ly : lx;
    float bsgn  = bx ? sx : sy;
    float delta = fminf(fmaxf(small - big, -10.0f), -0.001f);
    float diff  = __logf(1.0f - __expf(delta));
    bool  zr    = (small == big);
    float nl    = zr ? 0.0f : (big + diff);
    float ns    = zr ? 0.0f : bsgn;

    bool same = (sx * sy > 0.0f);

    float so_, lo_;
    if (!zx && !zy) { so_ = same ? s_same : ns;  lo_ = same ? l_same : nl; }
    else if (!zx)   { so_ = sx;                  lo_ = lx; }
    else if (!zy)   { so_ = sy;                  lo_ = ly; }
    else            { so_ = 0.0f;                lo_ = 0.0f; }

    so = so_;
    lo = clip_log(lo_);
}

__global__ __launch_bounds__(256)
void stack_machine_kernel(const float* __restrict__ sgn,
                          const float* __restrict__ logm,
                          const float* __restrict__ ops,
                          float* __restrict__ out,
                          int bt_total) {
    int bt = blockIdx.x * blockDim.x + threadIdx.x;
    if (bt >= bt_total) return;

    // Load the 32 log values for this (b,t) into registers (128B-aligned row).
    const float4* Lv = reinterpret_cast<const float4*>(logm + (size_t)bt * N_STACK);
    float l[N_STACK];
#pragma unroll
    for (int i = 0; i < N_STACK / 4; i++) {
        float4 v = Lv[i];
        l[4 * i + 0] = v.x; l[4 * i + 1] = v.y;
        l[4 * i + 2] = v.z; l[4 * i + 3] = v.w;
    }

    const float* S = sgn + (size_t)bt * N_STACK;
    const float* P = ops + (size_t)bt * DEPTH * 5;

    // Running sum of squares of buf_l[0 .. 30]. At step k, prev_logs are the
    // ORIGINAL values at indices 0..30-k (results written at step j land at
    // index 30-j and are consumed as `top` at step j+1, never re-read below).
    float SS = 0.0f;
#pragma unroll
    for (int i = 0; i < N_STACK - 1; i++) SS += l[i] * l[i];

    float rs = __ldg(S + (N_STACK - 1));  // running top sign
    float rl = l[N_STACK - 1];            // running top log

#pragma unroll
    for (int k = 0; k < DEPTH; k++) {
        const int si = N_STACK - 2 - k;   // sec index (original input)
        float ss_ = __ldg(S + si);
        float sl  = l[si];

        float p0 = __ldg(P + 5 * k + 0);
        float p1 = __ldg(P + 5 * k + 1);
        float p2 = __ldg(P + 5 * k + 2);
        float p3 = __ldg(P + 5 * k + 3);
        float p4 = __ldg(P + 5 * k + 4);

        // x = sec, y = top(res)
        float add_s, add_l, sub_s, sub_l;
        add_log(ss_, sl,  rs, rl, add_s, add_l);
        add_log(ss_, sl, -rs, rl, sub_s, sub_l);

        float muldiv_s = ss_ * rs;               // shared by mul and div
        float mul_l = clip_log(sl + rl);
        float div_l = clip_log(sl - rl);

        float nsgn = add_s * p0 + sub_s * p1 + muldiv_s * (p2 + p3) + ss_ * p4;
        float nlog = add_l * p0 + sub_l * p1 + mul_l * p2 + div_l * p3 + sl * p4;

        // RMS rescale over [prev_logs (len 31-k), nlog] -> len 32-k
        const float cs_inv = 1.0f / (float)(N_STACK - k);  // compile-time const
        float ms    = (SS + nlog * nlog) * cs_inv + 1e-6f;
        float scale = fminf(10.0f * rsqrtf(ms), 1.0f);

        rl = nlog * scale;
        rs = nsgn;
        SS -= sl * sl;   // drop sec from the prefix for the next step
    }

    out[bt]            = rs;  // stacked (sign, log) -> (2, B*T)
    out[bt_total + bt] = rl;
}

extern "C" void kernel_launch(void* const* d_in, const int* in_sizes, int n_in,
                              void* d_out, int out_size) {
    const float* sgn  = (const float*)d_in[0];
    const float* logm = (const float*)d_in[1];
    const float* ops  = (const float*)d_in[2];
    float* out = (float*)d_out;

    int bt_total = out_size / 2;  // (2, B, T) output
    int threads = 256;
    int blocks = (bt_total + threads - 1) / threads;
    stack_machine_kernel<<<blocks, threads>>>(sgn, logm, ops, out, bt_total);
}